// round 7
// baseline (speedup 1.0000x reference)
#include <cuda_runtime.h>
#include <cuda_bf16.h>
#include <cstdint>

#define BB 16
#define SS 2048
#define DD 1024
#define HH 1024
#define RR 16
#define MTOT (BB*SS)   // 32768
#define NN2 2048       // Wa||Wu stacked rows

#if defined(__CUDA_ARCH_FEAT_SM103_ALL) || defined(__CUDA_ARCH_FEAT_SM100_ALL)
#define HAS_TCGEN05 1
#elif defined(__CUDA_ARCH_SPECIFIC__)
#if (__CUDA_ARCH_SPECIFIC__ == 1030) || (__CUDA_ARCH_SPECIFIC__ == 1000)
#define HAS_TCGEN05 1
#else
#define HAS_TCGEN05 0
#endif
#else
#define HAS_TCGEN05 0
#endif

// Scratch
__device__ float A_buf[(size_t)BB*SS*HH];
__device__ float U_buf[(size_t)BB*SS*HH];
__device__ float G_buf[(size_t)BB*SS*RR];

__device__ __align__(16) __nv_bfloat16 Xhi[(size_t)MTOT*DD];
__device__ __align__(16) __nv_bfloat16 Xlo[(size_t)MTOT*DD];
__device__ __align__(16) __nv_bfloat16 Whi[(size_t)NN2*DD];
__device__ __align__(16) __nv_bfloat16 Wlo[(size_t)NN2*DD];

// ============================ helpers ============================
__device__ __forceinline__ uint32_t smem_u32(const void* p) {
    uint32_t a;
    asm("{ .reg .u64 t; cvta.to.shared.u64 t, %1; cvt.u32.u64 %0, t; }" : "=r"(a) : "l"(p));
    return a;
}
#define SWZ64(o) ((o) ^ (((o) >> 3) & 0x30))

__device__ __forceinline__ uint32_t pack_bf16x2(float lo, float hi) {
    uint32_t r;
    asm("cvt.rn.bf16x2.f32 %0, %1, %2;" : "=r"(r) : "f"(hi), "f"(lo));
    return r;
}

#if HAS_TCGEN05

__device__ __forceinline__ uint32_t elect_one() {
    uint32_t r;
    asm volatile("{ .reg .pred p; elect.sync _|p, 0xFFFFFFFF; selp.b32 %0, 1, 0, p; }" : "=r"(r));
    return r;
}

#define TC_ALLOC(smem_addr, ncols) \
    asm volatile("tcgen05.alloc.cta_group::1.sync.aligned.shared::cta.b32 [%0], %1;" \
                 :: "r"(smem_addr), "r"(ncols) : "memory")
#define TC_DEALLOC(tmem, ncols) \
    asm volatile("tcgen05.dealloc.cta_group::1.sync.aligned.b32 %0, %1;" :: "r"(tmem), "r"(ncols))
#define TC_COMMIT(mbar) \
    asm volatile("tcgen05.commit.cta_group::1.mbarrier::arrive::one.shared::cluster.b64 [%0];" \
                 :: "r"(mbar) : "memory")
#define TC_FENCE_AFTER()  asm volatile("tcgen05.fence::after_thread_sync;" ::: "memory")
#define TC_WAIT_LD()      asm volatile("tcgen05.wait::ld.sync.aligned;" ::: "memory")
#define FENCE_ASYNC_SHARED() asm volatile("fence.proxy.async.shared::cta;" ::: "memory")

#define CP_ASYNC16(dst, src) \
    asm volatile("cp.async.cg.shared.global [%0], [%1], 16;" :: "r"(dst), "l"(src) : "memory")
#define CP_COMMIT()  asm volatile("cp.async.commit_group;" ::: "memory")
#define CP_WAIT(n)   asm volatile("cp.async.wait_group %0;" :: "n"(n) : "memory")

#define MBAR_INIT(addr, cnt) \
    asm volatile("mbarrier.init.shared.b64 [%0], %1;" :: "r"(addr), "r"(cnt) : "memory")

#define MBAR_WAIT_PARITY(addr, parity) do { \
    uint32_t _mbar = (uint32_t)(addr); \
    uint32_t _par  = (uint32_t)(parity); \
    uint32_t _done; \
    asm volatile("{\n\t.reg .pred p;\n\t" \
        "mbarrier.try_wait.parity.acquire.cta.shared::cta.b64 p, [%1], %2;\n\t" \
        "selp.b32 %0, 1, 0, p;\n\t}" \
        : "=r"(_done) : "r"(_mbar), "r"(_par) : "memory"); \
    if (!_done) { \
        asm volatile("{\n\t.reg .pred P1;\n\t" \
            "WAIT_LOOP_%=:\n\t" \
            "mbarrier.try_wait.parity.acquire.cta.shared::cta.b64 P1, [%0], %1, 0x989680;\n\t" \
            "@P1 bra.uni WAIT_DONE_%=;\n\t" \
            "bra.uni WAIT_LOOP_%=;\n\t" \
            "WAIT_DONE_%=:\n\t}" \
            :: "r"(_mbar), "r"(_par) : "memory"); \
    } \
} while (0)

#define TC_LD_32X32B_X32(r, tmem_addr) \
    asm volatile( \
        "tcgen05.ld.sync.aligned.32x32b.x32.b32 " \
        "{%0, %1, %2, %3, %4, %5, %6, %7, " \
        " %8, %9, %10, %11, %12, %13, %14, %15, " \
        " %16, %17, %18, %19, %20, %21, %22, %23, " \
        " %24, %25, %26, %27, %28, %29, %30, %31}, [%32];" \
        : "=r"((r)[0]),  "=r"((r)[1]),  "=r"((r)[2]),  "=r"((r)[3]), \
          "=r"((r)[4]),  "=r"((r)[5]),  "=r"((r)[6]),  "=r"((r)[7]), \
          "=r"((r)[8]),  "=r"((r)[9]),  "=r"((r)[10]), "=r"((r)[11]), \
          "=r"((r)[12]), "=r"((r)[13]), "=r"((r)[14]), "=r"((r)[15]), \
          "=r"((r)[16]), "=r"((r)[17]), "=r"((r)[18]), "=r"((r)[19]), \
          "=r"((r)[20]), "=r"((r)[21]), "=r"((r)[22]), "=r"((r)[23]), \
          "=r"((r)[24]), "=r"((r)[25]), "=r"((r)[26]), "=r"((r)[27]), \
          "=r"((r)[28]), "=r"((r)[29]), "=r"((r)[30]), "=r"((r)[31]) \
        : "r"(tmem_addr))

// SW64 K-major smem descriptor (layout=4, version=1, SBO=32, LBO=1) — 64B rows
__device__ __forceinline__ uint64_t make_desc_sw64(uint32_t addr) {
    const uint64_t base = (uint64_t(4) << 61) | (uint64_t(1) << 46)
                        | (uint64_t(32) << 32) | (uint64_t(1) << 16);
    return base | ((uint64_t)(addr >> 4) & 0x3FFF);
}

__device__ __forceinline__ void mma_f16_ss(uint32_t d, uint64_t ad, uint64_t bd,
                                           uint32_t idesc, uint32_t en) {
    asm volatile(
        "{\n\t.reg .pred p;\n\t"
        "setp.ne.u32 p, %4, 0;\n\t"
        "tcgen05.mma.cta_group::1.kind::f16 [%0], %1, %2, %3, {%5,%5,%5,%5}, p;\n\t}"
        :: "r"(d), "l"(ad), "l"(bd), "r"(idesc), "r"(en), "r"(0u) : "memory");
}

#endif // HAS_TCGEN05

// ============================================================================
// Kernel 0: merged fp32 -> split-bf16 convert (X and W in one launch)
// ============================================================================
#define XBLKS ((MTOT * (DD/4)) / 256)   // 32768
#define WBLKS ((NN2  * (DD/4)) / 256)   // 2048

__global__ __launch_bounds__(256)
void convert_all_kernel(const float* __restrict__ x,
                        const float* __restrict__ Wa, const float* __restrict__ Wu)
{
    const float* src;
    __nv_bfloat16 *dhi, *dlo;
    size_t idx;
    if (blockIdx.x < XBLKS) {
        idx = (size_t)blockIdx.x * 256 + threadIdx.x;
        src = x + idx * 4;
        dhi = Xhi; dlo = Xlo;
    } else {
        idx = (size_t)(blockIdx.x - XBLKS) * 256 + threadIdx.x;
        size_t row = idx >> 8, col4 = idx & 255;
        src = (row < HH) ? (Wa + row * DD + col4 * 4) : (Wu + (row - HH) * DD + col4 * 4);
        dhi = Whi; dlo = Wlo;
    }
    float4 p = __ldg((const float4*)src);
    uint32_t w0 = __float_as_uint(p.x), w1 = __float_as_uint(p.y);
    uint32_t w2 = __float_as_uint(p.z), w3 = __float_as_uint(p.w);
    uint32_t h01 = __byte_perm(w0, w1, 0x7632);
    uint32_t h23 = __byte_perm(w2, w3, 0x7632);
    float l0 = p.x - __uint_as_float(w0 & 0xFFFF0000u);
    float l1 = p.y - __uint_as_float(w1 & 0xFFFF0000u);
    float l2 = p.z - __uint_as_float(w2 & 0xFFFF0000u);
    float l3 = p.w - __uint_as_float(w3 & 0xFFFF0000u);
    *(uint2*)(dhi + idx * 4) = make_uint2(h01, h23);
    *(uint2*)(dlo + idx * 4) = make_uint2(pack_bf16x2(l0, l1), pack_bf16x2(l2, l3));
}

// ============================================================================
// Kernel 1: tcgen05 split-bf16 projection GEMM, 4-stage cp.async pipeline.
// Tile M=128, N=256, K-chunk=32 (SW64, 64B rows).
// ============================================================================
#define TM 128
#define TN 256
#define KC 32
#define NCHUNK (DD / KC)     // 32
#define NST 4

#define A_HI_OFF 0
#define A_LO_OFF 8192
#define B_HI_OFF 16384
#define B_LO_OFF 32768
#define STAGE_BYTES 49152
#define STAGE_BASE  1024
#define SMEM_TOTAL  (STAGE_BASE + NST * STAGE_BYTES)   // 197632

__global__ __launch_bounds__(256, 1)
void proj_gemm_tc(const float* __restrict__ ba, const float* __restrict__ bu)
{
#if HAS_TCGEN05
    extern __shared__ char smem[];
    const uint32_t smb = smem_u32(smem);

    const uint32_t IDESC =
        (1u << 4) | (1u << 7) | (1u << 10) | ((TN / 8) << 17) | ((TM / 16) << 24);

    const int tid  = threadIdx.x;
    const int wid  = tid >> 5;
    const int lane = tid & 31;

    const int n0 = blockIdx.x * TN;
    const int m0 = blockIdx.y * TM;
    const bool isA = (n0 < HH);
    const int ncol0 = isA ? n0 : (n0 - HH);
    const float* bias = (isA ? ba : bu) + ncol0;
    float* outb = isA ? A_buf : U_buf;

    if (wid == 0) TC_ALLOC(smb + 0, 256);
    if (tid == 0) {
#pragma unroll
        for (int s = 0; s < NST; s++) MBAR_INIT(smb + 8 + s * 8, 1);
    }
    __syncthreads();
    uint32_t tmem_base;
    asm volatile("ld.shared.b32 %0, [%1];" : "=r"(tmem_base) : "r"(smb + 0));

    uint32_t mb[NST];
#pragma unroll
    for (int s = 0; s < NST; s++) mb[s] = smb + 8 + s * 8;
    uint32_t ph[NST] = { 0, 0, 0, 0 };

    for (int c = 0; c < NCHUNK; ++c) {
        const int st = c & 3;
        if (c >= NST) { MBAR_WAIT_PARITY(mb[st], ph[st]); ph[st] ^= 1; }

        const uint32_t sb = smb + STAGE_BASE + st * STAGE_BYTES;
        const int kc0 = c * KC;

        // A: 128 rows x 32 bf16 (64B/row), hi+lo: 2+2 ops/thread
        {
            const uint32_t aHi = sb + A_HI_OFF, aLo = sb + A_LO_OFF;
#pragma unroll
            for (int j = 0; j < 2; j++) {
                int u = tid + j * 256;              // 0..511
                int row = u >> 2, cb = u & 3;
                uint32_t off = SWZ64((uint32_t)(row * 64 + cb * 16));
                const char* sH = (const char*)(Xhi + (size_t)(m0 + row) * DD + kc0) + cb * 16;
                const char* sL = (const char*)(Xlo + (size_t)(m0 + row) * DD + kc0) + cb * 16;
                CP_ASYNC16(aHi + off, sH);
                CP_ASYNC16(aLo + off, sL);
            }
        }
        // B: 256 rows x 32 bf16, hi+lo: 4+4 ops/thread
        {
            const uint32_t bHi = sb + B_HI_OFF, bLo = sb + B_LO_OFF;
#pragma unroll
            for (int j = 0; j < 4; j++) {
                int u = tid + j * 256;              // 0..1023
                int row = u >> 2, cb = u & 3;
                uint32_t off = SWZ64((uint32_t)(row * 64 + cb * 16));
                const char* sH = (const char*)(Whi + (size_t)(n0 + row) * DD + kc0) + cb * 16;
                const char* sL = (const char*)(Wlo + (size_t)(n0 + row) * DD + kc0) + cb * 16;
                CP_ASYNC16(bHi + off, sH);
                CP_ASYNC16(bLo + off, sL);
            }
        }
        CP_COMMIT();

        if (c >= 1) {
            CP_WAIT(1);             // loads for chunk c-1 complete
            __syncthreads();
            if (wid == 0) {
                FENCE_ASYNC_SHARED();
                if (elect_one()) {
                    const int cm = c - 1;
                    const uint32_t sbm = smb + STAGE_BASE + (cm & 3) * STAGE_BYTES;
                    uint64_t dAhi = make_desc_sw64(sbm + A_HI_OFF);
                    uint64_t dAlo = make_desc_sw64(sbm + A_LO_OFF);
                    uint64_t dBhi = make_desc_sw64(sbm + B_HI_OFF);
                    uint64_t dBlo = make_desc_sw64(sbm + B_LO_OFF);
#pragma unroll
                    for (int k = 0; k < 2; k++) {
                        uint32_t en0 = (cm > 0 || k > 0) ? 1u : 0u;
                        mma_f16_ss(tmem_base, dAhi + k * 2, dBhi + k * 2, IDESC, en0);
                        mma_f16_ss(tmem_base, dAhi + k * 2, dBlo + k * 2, IDESC, 1u);
                        mma_f16_ss(tmem_base, dAlo + k * 2, dBhi + k * 2, IDESC, 1u);
                    }
                    TC_COMMIT(mb[cm & 3]);
                }
            }
        }
    }

    // drain: MMA for the final chunk
    CP_WAIT(0);
    __syncthreads();
    if (wid == 0) {
        FENCE_ASYNC_SHARED();
        if (elect_one()) {
            const int cm = NCHUNK - 1;
            const uint32_t sbm = smb + STAGE_BASE + (cm & 3) * STAGE_BYTES;
            uint64_t dAhi = make_desc_sw64(sbm + A_HI_OFF);
            uint64_t dAlo = make_desc_sw64(sbm + A_LO_OFF);
            uint64_t dBhi = make_desc_sw64(sbm + B_HI_OFF);
            uint64_t dBlo = make_desc_sw64(sbm + B_LO_OFF);
#pragma unroll
            for (int k = 0; k < 2; k++) {
                mma_f16_ss(tmem_base, dAhi + k * 2, dBhi + k * 2, IDESC, 1u);
                mma_f16_ss(tmem_base, dAhi + k * 2, dBlo + k * 2, IDESC, 1u);
                mma_f16_ss(tmem_base, dAlo + k * 2, dBhi + k * 2, IDESC, 1u);
            }
            TC_COMMIT(mb[cm & 3]);
        }
    }
    // each stage has exactly one unwaited commit
#pragma unroll
    for (int s = 0; s < NST; s++) MBAR_WAIT_PARITY(mb[s], ph[s]);
    TC_FENCE_AFTER();
    __syncthreads();

    // ---- epilogue: TMEM -> (bias, sigmoid) -> smem transpose -> coalesced STG
    float* stg = (float*)(smem + STAGE_BASE);     // 128 x 65 fp32 staging
    const int half = wid >> 2;
    const int subw = wid & 3;
    const int rowl = subw * 32 + lane;

    for (int slab = 0; slab < 4; ++slab) {
        const int c0 = slab * 64;
        uint32_t regs[32];
        TC_LD_32X32B_X32(regs, tmem_base + c0 + half * 32);
        TC_WAIT_LD();
#pragma unroll
        for (int j = 0; j < 32; j++) {
            int n = c0 + half * 32 + j;
            float val = __uint_as_float(regs[j]) + __ldg(&bias[n]);
            if (isA) val = 1.f / (1.f + __expf(-val));
            stg[rowl * 65 + half * 32 + j] = val;
        }
        __syncthreads();
#pragma unroll
        for (int i = 0; i < 8; i++) {
            int idx = tid + i * 256;
            int row = idx >> 4, c4 = idx & 15;
            const float* src = &stg[row * 65 + c4 * 4];
            float4 vv;
            vv.x = src[0]; vv.y = src[1]; vv.z = src[2]; vv.w = src[3];
            *(float4*)(outb + (size_t)(m0 + row) * HH + ncol0 + c0 + c4 * 4) = vv;
        }
        __syncthreads();
    }

    if (wid == 0) TC_DEALLOC(tmem_base, 256);
#endif // HAS_TCGEN05
}

// ---------------------------------------------------------------------------
// Kernel 2: g projection (128 blocks x 256 threads, 1 row/thread)
// ---------------------------------------------------------------------------
__global__ __launch_bounds__(256)
void g_gemm_kernel(const float* __restrict__ x,
                   const float* __restrict__ Wg, const float* __restrict__ bg)
{
    __shared__ __align__(16) float Xs[16][260];
    __shared__ __align__(16) float Wgs[16][16];

    const int m0 = blockIdx.x * 256;
    const int tid = threadIdx.x;

    float acc[RR];
#pragma unroll
    for (int r = 0; r < RR; r++) acc[r] = 0.f;

    for (int d0 = 0; d0 < DD; d0 += 16) {
        {
            int d = tid >> 4, rr = tid & 15;
            Wgs[d][rr] = Wg[(size_t)rr * DD + d0 + d];
        }
#pragma unroll
        for (int p = 0; p < 4; p++) {
            int row = (tid >> 2) + p * 64;
            int dc  = (tid & 3) * 4;
            float4 v4 = *(const float4*)(x + (size_t)(m0 + row) * DD + d0 + dc);
            Xs[dc + 0][row] = v4.x;
            Xs[dc + 1][row] = v4.y;
            Xs[dc + 2][row] = v4.z;
            Xs[dc + 3][row] = v4.w;
        }
        __syncthreads();

#pragma unroll
        for (int d = 0; d < 16; d++) {
            float xv = Xs[d][tid];
#pragma unroll
            for (int r = 0; r < RR; r++)
                acc[r] = fmaf(xv, Wgs[d][r], acc[r]);
        }
        __syncthreads();
    }

    float* g0 = G_buf + (size_t)(m0 + tid) * RR;
#pragma unroll
    for (int r = 0; r < RR; r += 4) {
        float4 o0;
        o0.x = acc[r+0]+bg[r+0]; o0.y = acc[r+1]+bg[r+1];
        o0.z = acc[r+2]+bg[r+2]; o0.w = acc[r+3]+bg[r+3];
        *(float4*)(g0 + r) = o0;
    }
}

// ---------------------------------------------------------------------------
// Kernel 3: scan — 16 blocks x 512 threads (16 warps), 2 states/thread,
// TWO barriers per step. svg distributed via intra-warp shuffles.
// ---------------------------------------------------------------------------
__global__ __launch_bounds__(512, 1)
void scan_kernel(const float* __restrict__ u_mat, const float* __restrict__ v_mat,
                 float* __restrict__ out)
{
    __shared__ __align__(16) float s_sm[HH];
    __shared__ __align__(16) float part[16][17];

    const int b    = blockIdx.x;
    const int tid  = threadIdx.x;
    const int w    = tid >> 5;          // 0..15
    const int lane = tid & 31;
    const int r    = tid & 15;
    const int hg   = tid >> 4;          // 0..31

    float vA[16], vB[16], uA[16], uB[16];
#pragma unroll
    for (int k = 0; k < 16; k++) {
        vA[k] = v_mat[(size_t)(hg * 16 + k) * RR + r];
        vB[k] = v_mat[(size_t)(512 + hg * 16 + k) * RR + r];
        uA[k] = u_mat[(size_t)tid * RR + k];
        uB[k] = u_mat[(size_t)(tid + 512) * RR + k];
    }

    float s0 = 0.f, s1 = 0.f;
    s_sm[tid] = 0.f; s_sm[tid + 512] = 0.f;

    const size_t base = (size_t)b * SS;
    float a0c = A_buf[base * HH + tid], a1c = A_buf[base * HH + tid + 512];
    float u0c = U_buf[base * HH + tid], u1c = U_buf[base * HH + tid + 512];
    float gc  = G_buf[base * RR + r];
    __syncthreads();

    for (int t = 0; t < SS; t++) {
        // prefetch t+1
        float a0n = 0.f, a1n = 0.f, u0n = 0.f, u1n = 0.f, gn = 0.f;
        if (t + 1 < SS) {
            size_t o = base + t + 1;
            a0n = A_buf[o * HH + tid]; a1n = A_buf[o * HH + tid + 512];
            u0n = U_buf[o * HH + tid]; u1n = U_buf[o * HH + tid + 512];
            gn  = G_buf[o * RR + r];
        }

        // --- phase A: partial of (v^T s)[r] over this thread's 32 h's ---
        float pA = 0.f, pB = 0.f;
        {
            const float4* sp = (const float4*)&s_sm[hg * 16];
            float4 q0 = sp[0], q1 = sp[1], q2 = sp[2], q3 = sp[3];
            pA = fmaf(q0.x, vA[0], pA);  pB = fmaf(q0.y, vA[1], pB);
            pA = fmaf(q0.z, vA[2], pA);  pB = fmaf(q0.w, vA[3], pB);
            pA = fmaf(q1.x, vA[4], pA);  pB = fmaf(q1.y, vA[5], pB);
            pA = fmaf(q1.z, vA[6], pA);  pB = fmaf(q1.w, vA[7], pB);
            pA = fmaf(q2.x, vA[8], pA);  pB = fmaf(q2.y, vA[9], pB);
            pA = fmaf(q2.z, vA[10], pA); pB = fmaf(q2.w, vA[11], pB);
            pA = fmaf(q3.x, vA[12], pA); pB = fmaf(q3.y, vA[13], pB);
            pA = fmaf(q3.z, vA[14], pA); pB = fmaf(q3.w, vA[15], pB);
        }
        {
            const float4* sp = (const float4*)&s_sm[512 + hg * 16];
            float4 q0 = sp[0], q1 = sp[1], q2 = sp[2], q3 = sp[3];
            pA = fmaf(q0.x, vB[0], pA);  pB = fmaf(q0.y, vB[1], pB);
            pA = fmaf(q0.z, vB[2], pA);  pB = fmaf(q0.w, vB[3], pB);
            pA = fmaf(q1.x, vB[4], pA);  pB = fmaf(q1.y, vB[5], pB);
            pA = fmaf(q1.z, vB[6], pA);  pB = fmaf(q1.w, vB[7], pB);
            pA = fmaf(q2.x, vB[8], pA);  pB = fmaf(q2.y, vB[9], pB);
            pA = fmaf(q2.z, vB[10], pA); pB = fmaf(q2.w, vB[11], pB);
            pA = fmaf(q3.x, vB[12], pA); pB = fmaf(q3.y, vB[13], pB);
            pA = fmaf(q3.z, vB[14], pA); pB = fmaf(q3.w, vB[15], pB);
        }
        float p = pA + pB;
        p += __shfl_xor_sync(0xffffffffu, p, 16);   // fold hg pair -> warp total
        if (lane < 16) part[w][lane] = p;
        __syncthreads();   // bar1

        // --- phase B: every thread reduces the 16 warp-partials for its r ---
        float y0 = 0.f, y1 = 0.f, y2 = 0.f, y3 = 0.f;
#pragma unroll
        for (int k = 0; k < 16; k += 4) {
            y0 += part[k + 0][r];
            y1 += part[k + 1][r];
            y2 += part[k + 2][r];
            y3 += part[k + 3][r];
        }
        float svg = gc * ((y0 + y1) + (y2 + y3));
        // distribute all 16 svg values within the warp (lane k holds r=k)
        float cf[16];
#pragma unroll
        for (int k = 0; k < 16; k++)
            cf[k] = __shfl_sync(0xffffffffu, svg, k);

        // --- phase C: update both states ---
        s0 = fmaf(a0c, s0, u0c);
        s1 = fmaf(a1c, s1, u1c);
        float d0a = 0.f, d0b = 0.f, d1a = 0.f, d1b = 0.f;
#pragma unroll
        for (int k = 0; k < 16; k += 2) {
            d0a = fmaf(cf[k],     uA[k],     d0a);
            d0b = fmaf(cf[k + 1], uA[k + 1], d0b);
            d1a = fmaf(cf[k],     uB[k],     d1a);
            d1b = fmaf(cf[k + 1], uB[k + 1], d1b);
        }
        s0 += d0a + d0b;
        s1 += d1a + d1b;
        s_sm[tid] = s0;
        s_sm[tid + 512] = s1;

        a0c = a0n; a1c = a1n; u0c = u0n; u1c = u1n; gc = gn;
        __syncthreads();   // bar2: state visible for next phase A
    }

    out[(size_t)b * HH + tid] = s0;
    out[(size_t)b * HH + tid + 512] = s1;
}

// ---------------------------------------------------------------------------
extern "C" void kernel_launch(void* const* d_in, const int* in_sizes, int n_in,
                              void* d_out, int out_size)
{
    const float* x  = (const float*)d_in[0];
    const float* Wa = (const float*)d_in[1];
    const float* ba = (const float*)d_in[2];
    const float* Wg = (const float*)d_in[3];
    const float* bg = (const float*)d_in[4];
    const float* Wu = (const float*)d_in[5];
    const float* bu = (const float*)d_in[6];
    const float* u  = (const float*)d_in[7];
    const float* v  = (const float*)d_in[8];
    float* out = (float*)d_out;

    (void)in_sizes; (void)n_in; (void)out_size;

    cudaFuncSetAttribute(proj_gemm_tc, cudaFuncAttributeMaxDynamicSharedMemorySize, SMEM_TOTAL);

    convert_all_kernel<<<XBLKS + WBLKS, 256>>>(x, Wa, Wu);                 // pos 1
    g_gemm_kernel<<<MTOT / 256, 256>>>(x, Wg, bg);                         // pos 2
    proj_gemm_tc<<<dim3(NN2 / TN, MTOT / TM), 256, SMEM_TOTAL>>>(ba, bu);  // pos 3
    scan_kernel<<<BB, 512>>>(u, v, out);                                   // pos 4 (profiled slot)
}

// round 8
// speedup vs baseline: 1.3006x; 1.3006x over previous
#include <cuda_runtime.h>
#include <cuda_bf16.h>
#include <cstdint>

#define BB 16
#define SS 2048
#define DD 1024
#define HH 1024
#define RR 16
#define MTOT (BB*SS)   // 32768
#define NN2 2048       // Wa||Wu stacked rows

#if defined(__CUDA_ARCH_FEAT_SM103_ALL) || defined(__CUDA_ARCH_FEAT_SM100_ALL)
#define HAS_TCGEN05 1
#elif defined(__CUDA_ARCH_SPECIFIC__)
#if (__CUDA_ARCH_SPECIFIC__ == 1030) || (__CUDA_ARCH_SPECIFIC__ == 1000)
#define HAS_TCGEN05 1
#else
#define HAS_TCGEN05 0
#endif
#else
#define HAS_TCGEN05 0
#endif

// Scratch
__device__ float A_buf[(size_t)BB*SS*HH];
__device__ float U_buf[(size_t)BB*SS*HH];
__device__ float G_buf[(size_t)BB*SS*RR];

__device__ __align__(16) __nv_bfloat16 Xhi[(size_t)MTOT*DD];
__device__ __align__(16) __nv_bfloat16 Xlo[(size_t)MTOT*DD];
__device__ __align__(16) __nv_bfloat16 Whi[(size_t)NN2*DD];
__device__ __align__(16) __nv_bfloat16 Wlo[(size_t)NN2*DD];

// ============================ helpers ============================
__device__ __forceinline__ uint32_t smem_u32(const void* p) {
    uint32_t a;
    asm("{ .reg .u64 t; cvta.to.shared.u64 t, %1; cvt.u32.u64 %0, t; }" : "=r"(a) : "l"(p));
    return a;
}
#define SWZ128(o) ((o) ^ (((o) >> 3) & 0x70))

__device__ __forceinline__ uint32_t pack_bf16x2(float lo, float hi) {
    uint32_t r;
    asm("cvt.rn.bf16x2.f32 %0, %1, %2;" : "=r"(r) : "f"(hi), "f"(lo));
    return r;
}

#if HAS_TCGEN05

__device__ __forceinline__ uint32_t elect_one() {
    uint32_t r;
    asm volatile("{ .reg .pred p; elect.sync _|p, 0xFFFFFFFF; selp.b32 %0, 1, 0, p; }" : "=r"(r));
    return r;
}

#define TC_ALLOC(smem_addr, ncols) \
    asm volatile("tcgen05.alloc.cta_group::1.sync.aligned.shared::cta.b32 [%0], %1;" \
                 :: "r"(smem_addr), "r"(ncols) : "memory")
#define TC_DEALLOC(tmem, ncols) \
    asm volatile("tcgen05.dealloc.cta_group::1.sync.aligned.b32 %0, %1;" :: "r"(tmem), "r"(ncols))
#define TC_COMMIT(mbar) \
    asm volatile("tcgen05.commit.cta_group::1.mbarrier::arrive::one.shared::cluster.b64 [%0];" \
                 :: "r"(mbar) : "memory")
#define TC_FENCE_AFTER()  asm volatile("tcgen05.fence::after_thread_sync;" ::: "memory")
#define TC_WAIT_LD()      asm volatile("tcgen05.wait::ld.sync.aligned;" ::: "memory")
#define FENCE_ASYNC_SHARED() asm volatile("fence.proxy.async.shared::cta;" ::: "memory")

#define CP_ASYNC16(dst, src) \
    asm volatile("cp.async.cg.shared.global [%0], [%1], 16;" :: "r"(dst), "l"(src) : "memory")
#define CP_COMMIT()  asm volatile("cp.async.commit_group;" ::: "memory")
#define CP_WAIT(n)   asm volatile("cp.async.wait_group %0;" :: "n"(n) : "memory")

#define MBAR_INIT(addr, cnt) \
    asm volatile("mbarrier.init.shared.b64 [%0], %1;" :: "r"(addr), "r"(cnt) : "memory")

#define MBAR_WAIT_PARITY(addr, parity) do { \
    uint32_t _mbar = (uint32_t)(addr); \
    uint32_t _par  = (uint32_t)(parity); \
    uint32_t _done; \
    asm volatile("{\n\t.reg .pred p;\n\t" \
        "mbarrier.try_wait.parity.acquire.cta.shared::cta.b64 p, [%1], %2;\n\t" \
        "selp.b32 %0, 1, 0, p;\n\t}" \
        : "=r"(_done) : "r"(_mbar), "r"(_par) : "memory"); \
    if (!_done) { \
        asm volatile("{\n\t.reg .pred P1;\n\t" \
            "WAIT_LOOP_%=:\n\t" \
            "mbarrier.try_wait.parity.acquire.cta.shared::cta.b64 P1, [%0], %1, 0x989680;\n\t" \
            "@P1 bra.uni WAIT_DONE_%=;\n\t" \
            "bra.uni WAIT_LOOP_%=;\n\t" \
            "WAIT_DONE_%=:\n\t}" \
            :: "r"(_mbar), "r"(_par) : "memory"); \
    } \
} while (0)

#define TC_LD_32X32B_X32(r, tmem_addr) \
    asm volatile( \
        "tcgen05.ld.sync.aligned.32x32b.x32.b32 " \
        "{%0, %1, %2, %3, %4, %5, %6, %7, " \
        " %8, %9, %10, %11, %12, %13, %14, %15, " \
        " %16, %17, %18, %19, %20, %21, %22, %23, " \
        " %24, %25, %26, %27, %28, %29, %30, %31}, [%32];" \
        : "=r"((r)[0]),  "=r"((r)[1]),  "=r"((r)[2]),  "=r"((r)[3]), \
          "=r"((r)[4]),  "=r"((r)[5]),  "=r"((r)[6]),  "=r"((r)[7]), \
          "=r"((r)[8]),  "=r"((r)[9]),  "=r"((r)[10]), "=r"((r)[11]), \
          "=r"((r)[12]), "=r"((r)[13]), "=r"((r)[14]), "=r"((r)[15]), \
          "=r"((r)[16]), "=r"((r)[17]), "=r"((r)[18]), "=r"((r)[19]), \
          "=r"((r)[20]), "=r"((r)[21]), "=r"((r)[22]), "=r"((r)[23]), \
          "=r"((r)[24]), "=r"((r)[25]), "=r"((r)[26]), "=r"((r)[27]), \
          "=r"((r)[28]), "=r"((r)[29]), "=r"((r)[30]), "=r"((r)[31]) \
        : "r"(tmem_addr))

// SW128 K-major smem descriptor (layout=2, version=1, SBO=64, LBO=1)
__device__ __forceinline__ uint64_t make_desc_sw128(uint32_t addr) {
    const uint64_t base = (uint64_t(2) << 61) | (uint64_t(1) << 46)
                        | (uint64_t(64) << 32) | (uint64_t(1) << 16);
    return base | ((uint64_t)(addr >> 4) & 0x3FFF);
}

__device__ __forceinline__ void mma_f16_ss(uint32_t d, uint64_t ad, uint64_t bd,
                                           uint32_t idesc, uint32_t en) {
    asm volatile(
        "{\n\t.reg .pred p;\n\t"
        "setp.ne.u32 p, %4, 0;\n\t"
        "tcgen05.mma.cta_group::1.kind::f16 [%0], %1, %2, %3, {%5,%5,%5,%5}, p;\n\t}"
        :: "r"(d), "l"(ad), "l"(bd), "r"(idesc), "r"(en), "r"(0u) : "memory");
}

#endif // HAS_TCGEN05

// ============================================================================
// Kernel 0: merged fp32 -> split-bf16 convert (X and W in one launch)
// ============================================================================
#define XBLKS ((MTOT * (DD/4)) / 256)   // 32768
#define WBLKS ((NN2  * (DD/4)) / 256)   // 2048

__global__ __launch_bounds__(256)
void convert_all_kernel(const float* __restrict__ x,
                        const float* __restrict__ Wa, const float* __restrict__ Wu)
{
    const float* src;
    __nv_bfloat16 *dhi, *dlo;
    size_t idx;
    if (blockIdx.x < XBLKS) {
        idx = (size_t)blockIdx.x * 256 + threadIdx.x;
        src = x + idx * 4;
        dhi = Xhi; dlo = Xlo;
    } else {
        idx = (size_t)(blockIdx.x - XBLKS) * 256 + threadIdx.x;
        size_t row = idx >> 8, col4 = idx & 255;
        src = (row < HH) ? (Wa + row * DD + col4 * 4) : (Wu + (row - HH) * DD + col4 * 4);
        dhi = Whi; dlo = Wlo;
    }
    float4 p = __ldg((const float4*)src);
    uint32_t w0 = __float_as_uint(p.x), w1 = __float_as_uint(p.y);
    uint32_t w2 = __float_as_uint(p.z), w3 = __float_as_uint(p.w);
    uint32_t h01 = __byte_perm(w0, w1, 0x7632);
    uint32_t h23 = __byte_perm(w2, w3, 0x7632);
    float l0 = p.x - __uint_as_float(w0 & 0xFFFF0000u);
    float l1 = p.y - __uint_as_float(w1 & 0xFFFF0000u);
    float l2 = p.z - __uint_as_float(w2 & 0xFFFF0000u);
    float l3 = p.w - __uint_as_float(w3 & 0xFFFF0000u);
    *(uint2*)(dhi + idx * 4) = make_uint2(h01, h23);
    *(uint2*)(dlo + idx * 4) = make_uint2(pack_bf16x2(l0, l1), pack_bf16x2(l2, l3));
}

// ============================================================================
// Kernel 1: tcgen05 split-bf16 projection GEMM (R6 known-good: 2-stage, KC=64)
// ============================================================================
#define TM 128
#define TN 256
#define KC 64
#define NCHUNK (DD / KC)     // 16

#define A_HI_OFF 0
#define A_LO_OFF 16384
#define B_HI_OFF 32768
#define B_LO_OFF 65536
#define STAGE_BYTES 98304
#define STAGE_BASE  1024
#define SMEM_TOTAL  (STAGE_BASE + 2 * STAGE_BYTES)   // 197632

__global__ __launch_bounds__(256, 1)
void proj_gemm_tc(const float* __restrict__ ba, const float* __restrict__ bu)
{
#if HAS_TCGEN05
    extern __shared__ char smem[];
    const uint32_t smb = smem_u32(smem);

    const uint32_t IDESC =
        (1u << 4) | (1u << 7) | (1u << 10) | ((TN / 8) << 17) | ((TM / 16) << 24);

    const int tid  = threadIdx.x;
    const int wid  = tid >> 5;
    const int lane = tid & 31;

    const int n0 = blockIdx.x * TN;
    const int m0 = blockIdx.y * TM;
    const bool isA = (n0 < HH);
    const int ncol0 = isA ? n0 : (n0 - HH);
    const float* bias = (isA ? ba : bu) + ncol0;
    float* outb = isA ? A_buf : U_buf;

    if (wid == 0) TC_ALLOC(smb + 0, 256);
    if (tid == 0) {
        MBAR_INIT(smb + 8, 1);
        MBAR_INIT(smb + 16, 1);
    }
    __syncthreads();
    uint32_t tmem_base;
    asm volatile("ld.shared.b32 %0, [%1];" : "=r"(tmem_base) : "r"(smb + 0));

    const uint32_t mb[2] = { smb + 8, smb + 16 };
    uint32_t ph[2] = { 0, 0 };

    for (int c = 0; c < NCHUNK; ++c) {
        const int st = c & 1;
        const uint32_t sb = smb + STAGE_BASE + st * STAGE_BYTES;
        const int kc0 = c * KC;

        if (c >= 2) { MBAR_WAIT_PARITY(mb[st], ph[st]); ph[st] ^= 1; }

        // A tiles: 128 rows x 64 bf16 (hi & lo)
        {
            const uint32_t aHi = sb + A_HI_OFF, aLo = sb + A_LO_OFF;
#pragma unroll
            for (int j = 0; j < 4; j++) {
                int u = tid + j * 256;              // 0..1023
                int row = u >> 3, cb = u & 7;
                uint32_t off = SWZ128((uint32_t)(row * 128 + cb * 16));
                const char* sH = (const char*)(Xhi + (size_t)(m0 + row) * DD + kc0) + cb * 16;
                const char* sL = (const char*)(Xlo + (size_t)(m0 + row) * DD + kc0) + cb * 16;
                CP_ASYNC16(aHi + off, sH);
                CP_ASYNC16(aLo + off, sL);
            }
        }
        // B tiles: 256 rows x 64 bf16 (hi & lo)
        {
            const uint32_t bHi = sb + B_HI_OFF, bLo = sb + B_LO_OFF;
#pragma unroll
            for (int j = 0; j < 8; j++) {
                int u = tid + j * 256;              // 0..2047
                int row = u >> 3, cb = u & 7;
                uint32_t off = SWZ128((uint32_t)(row * 128 + cb * 16));
                const char* sH = (const char*)(Whi + (size_t)(n0 + row) * DD + kc0) + cb * 16;
                const char* sL = (const char*)(Wlo + (size_t)(n0 + row) * DD + kc0) + cb * 16;
                CP_ASYNC16(bHi + off, sH);
                CP_ASYNC16(bLo + off, sL);
            }
        }
        CP_COMMIT();
        CP_WAIT(0);
        __syncthreads();

        if (wid == 0) {
            FENCE_ASYNC_SHARED();
            if (elect_one()) {
                uint64_t dAhi = make_desc_sw128(sb + A_HI_OFF);
                uint64_t dAlo = make_desc_sw128(sb + A_LO_OFF);
                uint64_t dBhi = make_desc_sw128(sb + B_HI_OFF);
                uint64_t dBlo = make_desc_sw128(sb + B_LO_OFF);
#pragma unroll
                for (int k = 0; k < 4; k++) {
                    uint32_t en0 = (c > 0 || k > 0) ? 1u : 0u;
                    mma_f16_ss(tmem_base, dAhi + k * 2, dBhi + k * 2, IDESC, en0);
                    mma_f16_ss(tmem_base, dAhi + k * 2, dBlo + k * 2, IDESC, 1u);
                    mma_f16_ss(tmem_base, dAlo + k * 2, dBhi + k * 2, IDESC, 1u);
                }
                TC_COMMIT(mb[st]);
            }
        }
    }

    MBAR_WAIT_PARITY(mb[0], ph[0]);
    MBAR_WAIT_PARITY(mb[1], ph[1]);
    TC_FENCE_AFTER();
    __syncthreads();

    // epilogue
    float* stg = (float*)(smem + STAGE_BASE);
    const int half = wid >> 2;
    const int subw = wid & 3;
    const int rowl = subw * 32 + lane;

    for (int slab = 0; slab < 4; ++slab) {
        const int c0 = slab * 64;
        uint32_t regs[32];
        TC_LD_32X32B_X32(regs, tmem_base + c0 + half * 32);
        TC_WAIT_LD();
#pragma unroll
        for (int j = 0; j < 32; j++) {
            int n = c0 + half * 32 + j;
            float val = __uint_as_float(regs[j]) + __ldg(&bias[n]);
            if (isA) val = 1.f / (1.f + __expf(-val));
            stg[rowl * 65 + half * 32 + j] = val;
        }
        __syncthreads();
#pragma unroll
        for (int i = 0; i < 8; i++) {
            int idx = tid + i * 256;
            int row = idx >> 4, c4 = idx & 15;
            const float* src = &stg[row * 65 + c4 * 4];
            float4 vv;
            vv.x = src[0]; vv.y = src[1]; vv.z = src[2]; vv.w = src[3];
            *(float4*)(outb + (size_t)(m0 + row) * HH + ncol0 + c0 + c4 * 4) = vv;
        }
        __syncthreads();
    }

    if (wid == 0) TC_DEALLOC(tmem_base, 256);
#endif // HAS_TCGEN05
}

// ---------------------------------------------------------------------------
// Kernel 2: g projection (128 blocks x 256 threads, 1 row/thread)
// ---------------------------------------------------------------------------
__global__ __launch_bounds__(256)
void g_gemm_kernel(const float* __restrict__ x,
                   const float* __restrict__ Wg, const float* __restrict__ bg)
{
    __shared__ __align__(16) float Xs[16][260];
    __shared__ __align__(16) float Wgs[16][16];

    const int m0 = blockIdx.x * 256;
    const int tid = threadIdx.x;

    float acc[RR];
#pragma unroll
    for (int r = 0; r < RR; r++) acc[r] = 0.f;

    for (int d0 = 0; d0 < DD; d0 += 16) {
        {
            int d = tid >> 4, rr = tid & 15;
            Wgs[d][rr] = Wg[(size_t)rr * DD + d0 + d];
        }
#pragma unroll
        for (int p = 0; p < 4; p++) {
            int row = (tid >> 2) + p * 64;
            int dc  = (tid & 3) * 4;
            float4 v4 = *(const float4*)(x + (size_t)(m0 + row) * DD + d0 + dc);
            Xs[dc + 0][row] = v4.x;
            Xs[dc + 1][row] = v4.y;
            Xs[dc + 2][row] = v4.z;
            Xs[dc + 3][row] = v4.w;
        }
        __syncthreads();

#pragma unroll
        for (int d = 0; d < 16; d++) {
            float xv = Xs[d][tid];
#pragma unroll
            for (int r = 0; r < RR; r++)
                acc[r] = fmaf(xv, Wgs[d][r], acc[r]);
        }
        __syncthreads();
    }

    float* g0 = G_buf + (size_t)(m0 + tid) * RR;
#pragma unroll
    for (int r = 0; r < RR; r += 4) {
        float4 o0;
        o0.x = acc[r+0]+bg[r+0]; o0.y = acc[r+1]+bg[r+1];
        o0.z = acc[r+2]+bg[r+2]; o0.w = acc[r+3]+bg[r+3];
        *(float4*)(g0 + r) = o0;
    }
}

// ---------------------------------------------------------------------------
// Kernel 3: scan — R6 structure (1024 thr, 32 warps, 3 bars) + DEPTH-2
// prefetch (a/u/g for t+2 loaded at step t => ~2 steps of latency cover)
// + single-buffer svg (direct store, no reset).
// ---------------------------------------------------------------------------
__global__ __launch_bounds__(1024, 1)
void scan_kernel(const float* __restrict__ u_mat, const float* __restrict__ v_mat,
                 float* __restrict__ out)
{
    __shared__ __align__(16) float s_sm[HH];
    __shared__ __align__(16) float part[32][17];
    __shared__ __align__(16) float svg[16];
    __shared__ __align__(16) float g_sm[16];

    const int b    = blockIdx.x;
    const int tid  = threadIdx.x;
    const int wid  = tid >> 5;
    const int lane = tid & 31;
    const int r    = tid & 15;
    const int hg   = tid >> 4;

    float vreg[16], ureg[16];
#pragma unroll
    for (int k = 0; k < 16; k++) vreg[k] = v_mat[(size_t)(hg * 16 + k) * RR + r];
#pragma unroll
    for (int k = 0; k < 16; k++) ureg[k] = u_mat[(size_t)tid * RR + k];

    float s = 0.f;
    s_sm[tid] = 0.f;

    const size_t base = (size_t)b * SS;
    // prefetch steps 0 and 1
    float a0 = A_buf[(base + 0) * HH + tid];
    float u0 = U_buf[(base + 0) * HH + tid];
    float g0 = G_buf[(base + 0) * RR + r];
    float a1 = A_buf[(base + 1) * HH + tid];
    float u1 = U_buf[(base + 1) * HH + tid];
    float g1 = G_buf[(base + 1) * RR + r];
    __syncthreads();

    for (int t = 0; t < SS; t++) {
        // issue prefetch for t+2 (consumed two iterations later)
        float a2 = 0.f, u2 = 0.f, g2 = 0.f;
        if (t + 2 < SS) {
            size_t o = base + t + 2;
            a2 = A_buf[o * HH + tid];
            u2 = U_buf[o * HH + tid];
            g2 = G_buf[o * RR + r];
        }
        if (tid < 16) g_sm[tid] = g0;

        // --- phase A: partial of (v^T s)[r] over h = hg*16 .. hg*16+15 ---
        float sv[16];
        const float4* sp = (const float4*)&s_sm[hg * 16];
        float4 q0 = sp[0], q1 = sp[1], q2 = sp[2], q3 = sp[3];
        sv[0]=q0.x; sv[1]=q0.y; sv[2]=q0.z; sv[3]=q0.w;
        sv[4]=q1.x; sv[5]=q1.y; sv[6]=q1.z; sv[7]=q1.w;
        sv[8]=q2.x; sv[9]=q2.y; sv[10]=q2.z; sv[11]=q2.w;
        sv[12]=q3.x; sv[13]=q3.y; sv[14]=q3.z; sv[15]=q3.w;

        float accA = 0.f, accB = 0.f;
#pragma unroll
        for (int k = 0; k < 16; k += 2) {
            accA = fmaf(sv[k],     vreg[k],     accA);
            accB = fmaf(sv[k + 1], vreg[k + 1], accB);
        }
        float acc = accA + accB;
        acc += __shfl_xor_sync(0xffffffffu, acc, 16);
        if (lane < 16) part[wid][lane] = acc;
        __syncthreads();   // bar1

        // --- phase B: warp w (w<16) reduces 32 partials for residual w ---
        if (wid < 16) {
            float pv = part[lane][wid];
            pv += __shfl_xor_sync(0xffffffffu, pv, 16);
            pv += __shfl_xor_sync(0xffffffffu, pv, 8);
            pv += __shfl_xor_sync(0xffffffffu, pv, 4);
            pv += __shfl_xor_sync(0xffffffffu, pv, 2);
            pv += __shfl_xor_sync(0xffffffffu, pv, 1);
            if (lane == 0) svg[wid] = g_sm[wid] * pv;
        }
        __syncthreads();   // bar2

        // --- phase C: update state ---
        float cf[16];
        const float4* cp = (const float4*)&svg[0];
        float4 c0 = cp[0], c1 = cp[1], c2 = cp[2], c3 = cp[3];
        cf[0]=c0.x; cf[1]=c0.y; cf[2]=c0.z; cf[3]=c0.w;
        cf[4]=c1.x; cf[5]=c1.y; cf[6]=c1.z; cf[7]=c1.w;
        cf[8]=c2.x; cf[9]=c2.y; cf[10]=c2.z; cf[11]=c2.w;
        cf[12]=c3.x; cf[13]=c3.y; cf[14]=c3.z; cf[15]=c3.w;

        s = fmaf(a0, s, u0);
        float dA = 0.f, dB = 0.f;
#pragma unroll
        for (int k = 0; k < 16; k += 2) {
            dA = fmaf(cf[k],     ureg[k],     dA);
            dB = fmaf(cf[k + 1], ureg[k + 1], dB);
        }
        s += dA + dB;
        s_sm[tid] = s;
        a0 = a1; u0 = u1; g0 = g1;
        a1 = a2; u1 = u2; g1 = g2;
        __syncthreads();   // bar3
    }

    out[(size_t)b * HH + tid] = s;
}

// ---------------------------------------------------------------------------
extern "C" void kernel_launch(void* const* d_in, const int* in_sizes, int n_in,
                              void* d_out, int out_size)
{
    const float* x  = (const float*)d_in[0];
    const float* Wa = (const float*)d_in[1];
    const float* ba = (const float*)d_in[2];
    const float* Wg = (const float*)d_in[3];
    const float* bg = (const float*)d_in[4];
    const float* Wu = (const float*)d_in[5];
    const float* bu = (const float*)d_in[6];
    const float* u  = (const float*)d_in[7];
    const float* v  = (const float*)d_in[8];
    float* out = (float*)d_out;

    (void)in_sizes; (void)n_in; (void)out_size;

    cudaFuncSetAttribute(proj_gemm_tc, cudaFuncAttributeMaxDynamicSharedMemorySize, SMEM_TOTAL);

    convert_all_kernel<<<XBLKS + WBLKS, 256>>>(x, Wa, Wu);
    g_gemm_kernel<<<MTOT / 256, 256>>>(x, Wg, bg);
    proj_gemm_tc<<<dim3(NN2 / TN, MTOT / TM), 256, SMEM_TOTAL>>>(ba, bu);
    scan_kernel<<<BB, 1024>>>(u, v, out);
}